// round 12
// baseline (speedup 1.0000x reference)
#include <cuda_runtime.h>
#include <cuda_fp16.h>
#include <math.h>
#include <cstdint>

#define D1 512
#define D2 1024
#define NS 16
#define MTOT 16384
#define LMASK 4095

// ---------------- scratch (static device globals; no allocation) ----------------
__device__ __half g_xnh[(size_t)MTOT * D1], g_xnl[(size_t)MTOT * D1];
__device__ __half g_t0h[(size_t)MTOT * D2], g_t0l[(size_t)MTOT * D2];
__device__ __half g_t1h[(size_t)MTOT * D2], g_t1l[(size_t)MTOT * D2];
__device__ __half g_t2h[(size_t)MTOT * D2], g_t2l[(size_t)MTOT * D2];
__device__ __half g_t3h[(size_t)MTOT * D2], g_t3l[(size_t)MTOT * D2];
__device__ float g_cb[MTOT];
// transposed fp16 weights
__device__ __half g_wIR[3 * 2048 * D1];     // inp rows 0-1023, res rows 1024-2047
__device__ __half g_wCnv[3 * D2 * D2];
__device__ __half g_wCl[3 * D2 * D2];
__device__ __half g_wF1[3 * D2 * D2];
__device__ __half g_wOut[3 * D1 * D2];      // [koff][512][1024]
__device__ float g_biasIR[2048];

// ---------------- small math ----------------
__device__ __forceinline__ float softplus_f(float x) {
    return (x > 20.0f) ? x : log1pf(expf(x));
}
__device__ __forceinline__ float swish_f(float x) {
    return x / (1.0f + expf(-x));
}

// ---------------- ptx helpers ----------------
__device__ __forceinline__ uint32_t s2u(const void* p) {
    uint32_t a;
    asm("{ .reg .u64 t; cvta.to.shared.u64 t, %1; cvt.u32.u64 %0, t; }"
        : "=r"(a) : "l"(p));
    return a;
}
__device__ __forceinline__ void cp16(uint32_t saddr, const void* gaddr, uint32_t sz) {
    asm volatile("cp.async.cg.shared.global [%0], [%1], 16, %2;"
                 :: "r"(saddr), "l"(gaddr), "r"(sz) : "memory");
}
__device__ __forceinline__ void cp_commit() {
    asm volatile("cp.async.commit_group;" ::: "memory");
}
template <int N>
__device__ __forceinline__ void cp_wait() {
    asm volatile("cp.async.wait_group %0;" :: "n"(N) : "memory");
}
__device__ __forceinline__ void ldsm4(uint32_t* r, uint32_t addr) {
    asm volatile("ldmatrix.sync.aligned.m8n8.x4.shared.b16 {%0,%1,%2,%3}, [%4];"
                 : "=r"(r[0]), "=r"(r[1]), "=r"(r[2]), "=r"(r[3]) : "r"(addr));
}
__device__ __forceinline__ void hmma(float* d, const uint32_t* a, const uint32_t* b) {
    asm volatile(
        "mma.sync.aligned.m16n8k16.row.col.f32.f16.f16.f32 "
        "{%0,%1,%2,%3}, {%4,%5,%6,%7}, {%8,%9}, {%0,%1,%2,%3};"
        : "+f"(d[0]), "+f"(d[1]), "+f"(d[2]), "+f"(d[3])
        : "r"(a[0]), "r"(a[1]), "r"(a[2]), "r"(a[3]), "r"(b[0]), "r"(b[1]));
}

// ---------------- unified prep: weight transposes + rmsnorm + bias concat ----------------
// blocks [0,13824): wtq; [13824,22016): rmsnorm (2 rows each); [22016,22024): biasIR
__global__ __launch_bounds__(256) void prep(
    const float* __restrict__ x, const float* __restrict__ norm_w,
    const float* __restrict__ inp_w, const float* __restrict__ conv_w,
    const float* __restrict__ cl_w, const float* __restrict__ fc1_w,
    const float* __restrict__ res_w, const float* __restrict__ out_w,
    const float* __restrict__ inp_b, const float* __restrict__ res_b,
    __half* __restrict__ xnh, __half* __restrict__ xnl,
    __half* __restrict__ wIR, __half* __restrict__ wCnv,
    __half* __restrict__ wCl, __half* __restrict__ wF1,
    __half* __restrict__ wOut, float* __restrict__ biasIR) {
    __shared__ float tile[32][33];
    __shared__ float sred[2][4];
    int lb = blockIdx.x;
    int tid = threadIdx.x;
    if (lb < 13824) {
        const float* W; __half* T; int Cin, Cout, rowoff, rowtot, base;
        if (lb < 1536)       { W = inp_w;  T = wIR;  Cin = 512;  Cout = 1024; rowoff = 0;    rowtot = 2048; base = 0; }
        else if (lb < 4608)  { W = conv_w; T = wCnv; Cin = 1024; Cout = 1024; rowoff = 0;    rowtot = 1024; base = 1536; }
        else if (lb < 7680)  { W = cl_w;   T = wCl;  Cin = 1024; Cout = 1024; rowoff = 0;    rowtot = 1024; base = 4608; }
        else if (lb < 10752) { W = fc1_w;  T = wF1;  Cin = 1024; Cout = 1024; rowoff = 0;    rowtot = 1024; base = 7680; }
        else if (lb < 12288) { W = res_w;  T = wIR;  Cin = 512;  Cout = 1024; rowoff = 1024; rowtot = 2048; base = 10752; }
        else                 { W = out_w;  T = wOut; Cin = 1024; Cout = 512;  rowoff = 0;    rowtot = 512;  base = 12288; }
        int l = lb - base;
        int nx = Cout / 32;
        int bx = l % nx;
        int rest = l / nx;
        int ny = Cin / 32;
        int by = rest % ny;
        int koff = rest / ny;
        int n0 = bx * 32, c0 = by * 32;
        int tx = tid & 31, ty = tid >> 5;
        const float* Wk = W + (size_t)koff * Cin * Cout;
#pragma unroll
        for (int r = 0; r < 32; r += 8)
            tile[ty + r][tx] = Wk[(size_t)(c0 + ty + r) * Cout + n0 + tx];
        __syncthreads();
        __half* Tk = T + (size_t)koff * rowtot * Cin;
#pragma unroll
        for (int r = 0; r < 32; r += 8)
            Tk[(size_t)(rowoff + n0 + ty + r) * Cin + c0 + tx] =
                __float2half_rn(tile[tx][ty + r]);
    } else if (lb < 22016) {
        int rb = lb - 13824;
        int row = rb * 2 + (tid >> 7);
        int t = tid & 127;
        int sr = tid >> 7;
        const float4* xr = (const float4*)(x + (size_t)row * D1);
        float4 xv = xr[t];
        float ss = xv.x * xv.x + xv.y * xv.y + xv.z * xv.z + xv.w * xv.w;
#pragma unroll
        for (int off = 16; off; off >>= 1)
            ss += __shfl_xor_sync(0xffffffffu, ss, off);
        if ((t & 31) == 0) sred[sr][t >> 5] = ss;
        __syncthreads();
        float tot = sred[sr][0] + sred[sr][1] + sred[sr][2] + sred[sr][3];
        float s = rsqrtf(tot * (1.0f / (float)D1) + 1e-5f);
        float4 wv = ((const float4*)norm_w)[t];
        float o[4];
        o[0] = xv.x * s * wv.x; o[1] = xv.y * s * wv.y;
        o[2] = xv.z * s * wv.z; o[3] = xv.w * s * wv.w;
        size_t base = (size_t)row * D1 + t * 4;
#pragma unroll
        for (int j = 0; j < 4; j += 2) {
            __half h0 = __float2half_rn(o[j]);
            __half h1 = __float2half_rn(o[j + 1]);
            __half2 hp; hp.x = h0; hp.y = h1;
            *(__half2*)(xnh + base + j) = hp;
            __half2 lp;
            lp.x = __float2half_rn(o[j] - __half2float(h0));
            lp.y = __float2half_rn(o[j + 1] - __half2float(h1));
            *(__half2*)(xnl + base + j) = lp;
        }
    } else {
        int i = (lb - 22016) * 256 + tid;
        biasIR[i] = (i < D2) ? inp_b[i] : res_b[i - D2];
    }
}

// ---------------- fp16 conv-GEMM (mma.sync), 2 CTAs/SM, warp tile 32x64 ----------------
// Y[m,n] = act( sum_{koff,c} X[m+koff-1,c] * WT[koff][n][c] + bias[n] )
// X = Xh + Xl (fp16 split), W = fp16. 2 HMMAs per k16.
// kc-granular pipeline: one iteration = one 130-row A tile + 3 koff B tiles
// = 192 HMMAs/warp between barriers. 2-stage ring (parity kc&1) for both.
// Ordering per iter: wait<0> -> barrier -> issue(kc+1) -> compute.
// WAR safety: issue writes the opposite-parity slots, whose last readers
// were iteration kc-1, provably done before this barrier.
#define ASTR 80                      // bytes per smem row (32 halfs + 16B pad)
#define A_SLOT (130 * ASTR * 2)      // 20800: hi plane then lo plane (130 rows each)
#define A_PL (130 * ASTR)            // 10400
#define B_BASE (2 * A_SLOT)          // 41600
#define B_SLOT (128 * ASTR)          // 10240
#define B_GRP (3 * B_SLOT)           // 30720: koff 0,1,2 tiles
#define GEMM_SMEM (B_BASE + 2 * B_GRP)  // 103040

// ACT: 0 none, 1 swish, 2 s6 epilogue, 3 dual (plain->Y / swish->Y2, stride D2).
// OUTF: 0 split fp16, 1 fp32.
template <int ACT, int OUTF>
__global__ __launch_bounds__(256, 2) void mm_h(
    const __half* __restrict__ Ah, const __half* __restrict__ Al,
    const __half* __restrict__ Wt,
    const float* __restrict__ bias, int Cin, int Cout, int M,
    __half* __restrict__ Yh, __half* __restrict__ Yl, float* __restrict__ Yf,
    __half* __restrict__ Y2h, __half* __restrict__ Y2l,
    const __half* __restrict__ xch, const __half* __restrict__ xcl,
    const __half* __restrict__ xrh, const __half* __restrict__ xrl,
    const float* __restrict__ cbv) {
    extern __shared__ char smem[];
    const uint32_t sb = s2u(smem);
    const int tid = threadIdx.x;
    const int wid = tid >> 5;
    const int lane = tid & 31;
    const int warp_m = wid >> 1;   // 0..3 (32 rows each)
    const int warp_n = wid & 1;    // 0..1 (64 cols each)
    const int bm = blockIdx.y * 128;
    const int bn = blockIdx.x * 128;
    const int KC = Cin >> 5;       // 32-wide k chunks

    float acc[2][8][4];
#pragma unroll
    for (int i = 0; i < 2; i++)
#pragma unroll
        for (int j = 0; j < 8; j++)
#pragma unroll
            for (int q = 0; q < 4; q++) acc[i][j][q] = 0.f;

    // A loader: thread t < 130 loads tile row t (= input row bm-1+t), 64B/plane.
    // Row 0 is only consumed via koff=0 by output bm; row 129 only via koff=2
    // by output bm+127 -> zero them exactly at batch boundaries.
    const bool a_active = tid < 130;
    bool a_valid = true;
    long long a_grow = (long long)bm - 1 + tid;
    if (tid == 0 && (bm & LMASK) == 0) a_valid = false;
    if (tid == 129 && ((bm + 128) & LMASK) == 0) a_valid = false;
    if (a_grow < 0) a_grow = 0;
    if (a_grow >= M) a_grow = M - 1;
    const uint32_t a_sz = a_valid ? 16u : 0u;

    auto issueA = [&](int kc) {
        if (!a_active) return;
        uint32_t dst = sb + (uint32_t)(kc & 1) * A_SLOT + (uint32_t)tid * ASTR;
        const __half* ph = Ah + a_grow * Cin + kc * 32;
        const __half* pl = Al + a_grow * Cin + kc * 32;
#pragma unroll
        for (int i = 0; i < 4; i++) {
            cp16(dst + i * 16, ph + i * 8, a_sz);
            cp16(dst + A_PL + i * 16, pl + i * 8, a_sz);
        }
    };

    // B loader: 2 threads per row, 32B each; all 3 koff tiles of one kc.
    const int blr = tid >> 1;
    const int blseg = tid & 1;
    auto issueBg = [&](int kc) {
        uint32_t dst = sb + B_BASE + (uint32_t)(kc & 1) * B_GRP +
                       (uint32_t)blr * ASTR + (uint32_t)blseg * 32;
#pragma unroll
        for (int koff = 0; koff < 3; koff++) {
            size_t bo = ((size_t)koff * Cout + bn + blr) * Cin + kc * 32 + blseg * 16;
            cp16(dst + (uint32_t)koff * B_SLOT, Wt + bo, 16u);
            cp16(dst + (uint32_t)koff * B_SLOT + 16, Wt + bo + 8, 16u);
        }
    };

    // prologue: group 0
    issueA(0); issueBg(0); cp_commit();

    // ldmatrix address components
    const int a_row = warp_m * 32 + (lane & 15);   // local output row (frag)
    const uint32_t a_kb = (uint32_t)(lane >> 4) * 16;
    const int mi = lane >> 3;
    const int b_row = warp_n * 64 + ((mi >> 1) << 3) + (lane & 7);
    const uint32_t b_kb = (uint32_t)(mi & 1) * 16;

    for (int kc = 0; kc < KC; kc++) {
        cp_wait<0>();
        __syncthreads();
        if (kc + 1 < KC) {
            issueA(kc + 1);
            issueBg(kc + 1);
            cp_commit();
        }

        const uint32_t abase = sb + (uint32_t)(kc & 1) * A_SLOT;
        const uint32_t bgrp = sb + B_BASE + (uint32_t)(kc & 1) * B_GRP;

#pragma unroll
        for (int koff = 0; koff < 3; koff++) {
            const uint32_t bbase = bgrp + (uint32_t)koff * B_SLOT;
#pragma unroll
            for (int k16 = 0; k16 < 2; k16++) {
                uint32_t ah[2][4], al[2][4];
#pragma unroll
                for (int mt = 0; mt < 2; mt++) {
                    uint32_t addr = abase +
                                    (uint32_t)(a_row + mt * 16 + koff) * ASTR +
                                    (uint32_t)k16 * 32 + a_kb;
                    ldsm4(ah[mt], addr);
                    ldsm4(al[mt], addr + A_PL);
                }
                uint32_t bf[8][2];
#pragma unroll
                for (int p = 0; p < 4; p++) {
                    uint32_t addr = bbase + (uint32_t)(b_row + p * 16) * ASTR +
                                    (uint32_t)k16 * 32 + b_kb;
                    uint32_t t4[4];
                    ldsm4(t4, addr);
                    bf[2 * p][0] = t4[0]; bf[2 * p][1] = t4[1];
                    bf[2 * p + 1][0] = t4[2]; bf[2 * p + 1][1] = t4[3];
                }
#pragma unroll
                for (int mt = 0; mt < 2; mt++)
#pragma unroll
                    for (int nt = 0; nt < 8; nt++)
                        hmma(acc[mt][nt], ah[mt], bf[nt]);
#pragma unroll
                for (int mt = 0; mt < 2; mt++)
#pragma unroll
                    for (int nt = 0; nt < 8; nt++)
                        hmma(acc[mt][nt], al[mt], bf[nt]);
            }
        }
    }

    // ---------------- epilogue ----------------
    const int erow0 = bm + warp_m * 32 + (lane >> 2);
    const int ecol0 = bn + warp_n * 64 + (lane & 3) * 2;
    const bool isres = (ACT == 3) && (bn >= D2);
    const __half* obh = (ACT == 3) ? (isres ? Y2h : Yh) : Yh;
    const __half* obl = (ACT == 3) ? (isres ? Y2l : Yl) : Yl;
    const int coff = isres ? D2 : 0;
    const int ostride = (ACT == 3) ? D2 : Cout;
#pragma unroll
    for (int mt = 0; mt < 2; mt++) {
#pragma unroll
        for (int h = 0; h < 2; h++) {
            int row = erow0 + mt * 16 + h * 8;
            float cbs = 0.f;
            if (ACT == 2) cbs = cbv[row];
            size_t yb = (size_t)row * ostride;
#pragma unroll
            for (int nt = 0; nt < 8; nt++) {
                int col = ecol0 + nt * 8;
                float v0 = acc[mt][nt][2 * h + 0] + bias[col];
                float v1 = acc[mt][nt][2 * h + 1] + bias[col + 1];
                if (ACT == 1) { v0 = swish_f(v0); v1 = swish_f(v1); }
                if (ACT == 3 && isres) { v0 = swish_f(v0); v1 = swish_f(v1); }
                if (ACT == 2) {
                    size_t o = yb + col;
                    __half2 ch = *(const __half2*)(xch + o);
                    __half2 cl = *(const __half2*)(xcl + o);
                    __half2 rh = *(const __half2*)(xrh + o);
                    __half2 rl = *(const __half2*)(xrl + o);
                    float xc0 = __half2float(ch.x) + __half2float(cl.x);
                    float xc1 = __half2float(ch.y) + __half2float(cl.y);
                    float xr0 = __half2float(rh.x) + __half2float(rl.x);
                    float xr1 = __half2float(rh.y) + __half2float(rl.y);
                    v0 = xc0 * softplus_f(v0) * cbs * xr0;
                    v1 = xc1 * softplus_f(v1) * cbs * xr1;
                }
                if (OUTF == 0) {
                    size_t o = yb + col - coff;
                    __half h0 = __float2half_rn(v0);
                    __half h1 = __float2half_rn(v1);
                    __half2 hp; hp.x = h0; hp.y = h1;
                    *(__half2*)((__half*)obh + o) = hp;
                    __half2 lp;
                    lp.x = __float2half_rn(v0 - __half2float(h0));
                    lp.y = __float2half_rn(v1 - __half2float(h1));
                    *(__half2*)((__half*)obl + o) = lp;
                } else {
                    *(float2*)(Yf + yb + col) = make_float2(v0, v1);
                }
            }
        }
    }
}

// ---------------- bc: cb[m] = sum_n (conv16(fc2)+b2)*(conv16(fc3)+b3) ----------------
#define BC_SMEM (2 * 3 * D2 * NS * 2)   // 196608 bytes
__global__ __launch_bounds__(256, 1) void bc2(
    const __half* __restrict__ Xh, const __half* __restrict__ Xl,
    const float* __restrict__ w2, const float* __restrict__ b2,
    const float* __restrict__ w3, const float* __restrict__ b3,
    float* __restrict__ cbout, int M) {
    extern __shared__ __half ws[];
    __half* w2s = ws;
    __half* w3s = ws + 3 * D2 * NS;
    const int tid = threadIdx.x;
    const int wid = tid >> 5;
    const int lane = tid & 31;
    const int bm = blockIdx.x * 128;

    for (int i = tid; i < 3 * D2 * NS; i += 256) {
        w2s[i] = __float2half_rn(w2[i]);
        w3s[i] = __float2half_rn(w3[i]);
    }
    __syncthreads();

    for (int g = 0; g < 4; g++) {
        int r0 = bm + wid * 16 + g * 4;
        float accB[4][NS], accC[4][NS];
#pragma unroll
        for (int j = 0; j < 4; j++)
#pragma unroll
            for (int n = 0; n < NS; n++) { accB[j][n] = 0.f; accC[j][n] = 0.f; }

        for (int koff = 0; koff < 3; koff++) {
            const __half* xh0 = Xh + (size_t)(r0 + koff - 1) * D2;
            const __half* xl0 = Xl + (size_t)(r0 + koff - 1) * D2;
            bool val[4];
#pragma unroll
            for (int j = 0; j < 4; j++) {
                int pos = (r0 + j) & LMASK;
                val[j] = !((koff == 0 && pos == 0) || (koff == 2 && pos == LMASK));
            }
            const __half* w2k = w2s + koff * D2 * NS;
            const __half* w3k = w3s + koff * D2 * NS;
            for (int kk = lane; kk < D2; kk += 32) {
                float xv[4];
#pragma unroll
                for (int j = 0; j < 4; j++) {
                    size_t o = (size_t)j * D2 + kk;
                    xv[j] = val[j] ? (__half2float(xh0[o]) + __half2float(xl0[o]))
                                   : 0.f;
                }
                const __half2* wb = (const __half2*)(w2k + kk * NS);
                const __half2* wc = (const __half2*)(w3k + kk * NS);
#pragma unroll
                for (int q = 0; q < 8; q++) {
                    float2 fb = __half22float2(wb[q]);
                    float2 fc = __half22float2(wc[q]);
#pragma unroll
                    for (int j = 0; j < 4; j++) {
                        accB[j][2 * q] += xv[j] * fb.x;
                        accB[j][2 * q + 1] += xv[j] * fb.y;
                        accC[j][2 * q] += xv[j] * fc.x;
                        accC[j][2 * q + 1] += xv[j] * fc.y;
                    }
                }
            }
        }
#pragma unroll
        for (int j = 0; j < 4; j++) {
#pragma unroll
            for (int n = 0; n < NS; n++) {
#pragma unroll
                for (int off = 16; off; off >>= 1) {
                    accB[j][n] += __shfl_xor_sync(0xffffffffu, accB[j][n], off);
                    accC[j][n] += __shfl_xor_sync(0xffffffffu, accC[j][n], off);
                }
            }
            if (lane == 0) {
                float s = 0.f;
#pragma unroll
                for (int n = 0; n < NS; n++)
                    s += (accB[j][n] + b2[n]) * (accC[j][n] + b3[n]);
                cbout[r0 + j] = s;
            }
        }
    }
}

// ---------------- launch ----------------
extern "C" void kernel_launch(void* const* d_in, const int* in_sizes, int n_in,
                              void* d_out, int out_size) {
    const float* x      = (const float*)d_in[0];
    const float* norm_w = (const float*)d_in[1];
    const float* inp_w  = (const float*)d_in[2];
    const float* inp_b  = (const float*)d_in[3];
    const float* conv_w = (const float*)d_in[4];
    const float* conv_b = (const float*)d_in[5];
    const float* cl_w   = (const float*)d_in[6];
    const float* cl_b   = (const float*)d_in[7];
    const float* fc1_w  = (const float*)d_in[8];
    const float* fc1_b  = (const float*)d_in[9];
    const float* fc2_w  = (const float*)d_in[10];
    const float* fc2_b  = (const float*)d_in[11];
    const float* fc3_w  = (const float*)d_in[12];
    const float* fc3_b  = (const float*)d_in[13];
    // d_in[14] = A (mathematically dead)
    const float* res_w  = (const float*)d_in[15];
    const float* res_b  = (const float*)d_in[16];
    const float* out_w  = (const float*)d_in[17];
    const float* out_b  = (const float*)d_in[18];

    int M = in_sizes[0] / D1;  // 16384

    __half *xnh, *xnl, *t0h, *t0l, *t1h, *t1l, *t2h, *t2l, *t3h, *t3l;
    __half *wIR, *wCnv, *wCl, *wF1, *wOut;
    float *cb, *biasIR;
    cudaGetSymbolAddress((void**)&xnh, g_xnh);
    cudaGetSymbolAddress((void**)&xnl, g_xnl);
    cudaGetSymbolAddress((void**)&t0h, g_t0h);
    cudaGetSymbolAddress((void**)&t0l, g_t0l);
    cudaGetSymbolAddress((void**)&t1h, g_t1h);
    cudaGetSymbolAddress((void**)&t1l, g_t1l);
    cudaGetSymbolAddress((void**)&t2h, g_t2h);
    cudaGetSymbolAddress((void**)&t2l, g_t2l);
    cudaGetSymbolAddress((void**)&t3h, g_t3h);
    cudaGetSymbolAddress((void**)&t3l, g_t3l);
    cudaGetSymbolAddress((void**)&cb, g_cb);
    cudaGetSymbolAddress((void**)&wIR, g_wIR);
    cudaGetSymbolAddress((void**)&wCnv, g_wCnv);
    cudaGetSymbolAddress((void**)&wCl, g_wCl);
    cudaGetSymbolAddress((void**)&wF1, g_wF1);
    cudaGetSymbolAddress((void**)&wOut, g_wOut);
    cudaGetSymbolAddress((void**)&biasIR, g_biasIR);

    cudaFuncSetAttribute(mm_h<0, 0>, cudaFuncAttributeMaxDynamicSharedMemorySize, GEMM_SMEM);
    cudaFuncSetAttribute(mm_h<1, 0>, cudaFuncAttributeMaxDynamicSharedMemorySize, GEMM_SMEM);
    cudaFuncSetAttribute(mm_h<2, 0>, cudaFuncAttributeMaxDynamicSharedMemorySize, GEMM_SMEM);
    cudaFuncSetAttribute(mm_h<3, 0>, cudaFuncAttributeMaxDynamicSharedMemorySize, GEMM_SMEM);
    cudaFuncSetAttribute(mm_h<0, 1>, cudaFuncAttributeMaxDynamicSharedMemorySize, GEMM_SMEM);
    cudaFuncSetAttribute(bc2, cudaFuncAttributeMaxDynamicSharedMemorySize, BC_SMEM);

    // 1) prep: all weight transposes + rmsnorm + bias concat (one launch)
    prep<<<22024, 256>>>(x, norm_w, inp_w, conv_w, cl_w, fc1_w, res_w, out_w,
                         inp_b, res_b, xnh, xnl, wIR, wCnv, wCl, wF1, wOut, biasIR);

    dim3 blk(256);
    dim3 g_fuse(2048 / 128, M / 128);  // 16 x 128
    dim3 g_big(D2 / 128, M / 128);     // 8 x 128
    dim3 g_out(D1 / 128, M / 128);     // 4 x 128

    // 2) fused: t0 = conv(xn, inp) [cols 0-1023]; t3 = swish(conv(xn, res)) [cols 1024-2047]
    mm_h<3, 0><<<g_fuse, blk, GEMM_SMEM>>>(xnh, xnl, wIR, biasIR, D1, 2048, M,
        t0h, t0l, nullptr, t3h, t3l, nullptr, nullptr, nullptr, nullptr, nullptr);
    // 3) t1 = swish(conv(t0, conv))
    mm_h<1, 0><<<g_big, blk, GEMM_SMEM>>>(t0h, t0l, wCnv, conv_b, D2, D2, M,
        t1h, t1l, nullptr, nullptr, nullptr, nullptr, nullptr, nullptr, nullptr, nullptr);
    // 4) t2 = conv(t1, cl) = x_conv_out
    mm_h<0, 0><<<g_big, blk, GEMM_SMEM>>>(t1h, t1l, wCl, cl_b, D2, D2, M,
        t2h, t2l, nullptr, nullptr, nullptr, nullptr, nullptr, nullptr, nullptr, nullptr);
    // 5) cb[m]
    bc2<<<M / 128, 256, BC_SMEM>>>(t2h, t2l, fc2_w, fc2_b, fc3_w, fc3_b, cb, M);
    // 6) t0 = x_ssm * x_res (s6 epilogue; xc = t2, xr = t3)
    mm_h<2, 0><<<g_big, blk, GEMM_SMEM>>>(t2h, t2l, wF1, fc1_b, D2, D2, M,
        t0h, t0l, nullptr, nullptr, nullptr, t2h, t2l, t3h, t3l, cb);
    // 7) out = conv(t0, out) -> fp32 d_out
    mm_h<0, 1><<<g_out, blk, GEMM_SMEM>>>(t0h, t0l, wOut, out_b, D2, D1, M,
        nullptr, nullptr, (float*)d_out, nullptr, nullptr, nullptr, nullptr, nullptr, nullptr, nullptr);
}

// round 13
// speedup vs baseline: 1.0255x; 1.0255x over previous
#include <cuda_runtime.h>
#include <cuda_fp16.h>
#include <math.h>
#include <cstdint>

#define D1 512
#define D2 1024
#define NS 16
#define MTOT 16384
#define LMASK 4095

// ---------------- scratch (static device globals; no allocation) ----------------
__device__ __half g_xnh[(size_t)MTOT * D1], g_xnl[(size_t)MTOT * D1];
__device__ __half g_t0h[(size_t)MTOT * D2], g_t0l[(size_t)MTOT * D2];
__device__ __half g_t1h[(size_t)MTOT * D2], g_t1l[(size_t)MTOT * D2];
__device__ __half g_t2h[(size_t)MTOT * D2], g_t2l[(size_t)MTOT * D2];
__device__ __half g_t3h[(size_t)MTOT * D2], g_t3l[(size_t)MTOT * D2];
__device__ float g_cb[MTOT];
// transposed fp16 weights
__device__ __half g_wIR[3 * 2048 * D1];     // inp rows 0-1023, res rows 1024-2047
__device__ __half g_wCnv[3 * D2 * D2];
__device__ __half g_wCl[3 * D2 * D2];
__device__ __half g_wF1[3 * D2 * D2];
__device__ __half g_wOut[3 * D1 * D2];      // [koff][512][1024]
__device__ float g_biasIR[2048];

// ---------------- small math ----------------
__device__ __forceinline__ float softplus_f(float x) {
    return (x > 20.0f) ? x : log1pf(expf(x));
}
__device__ __forceinline__ float swish_f(float x) {
    return x / (1.0f + expf(-x));
}

// ---------------- ptx helpers ----------------
__device__ __forceinline__ uint32_t s2u(const void* p) {
    uint32_t a;
    asm("{ .reg .u64 t; cvta.to.shared.u64 t, %1; cvt.u32.u64 %0, t; }"
        : "=r"(a) : "l"(p));
    return a;
}
__device__ __forceinline__ void cp16(uint32_t saddr, const void* gaddr, uint32_t sz) {
    asm volatile("cp.async.cg.shared.global [%0], [%1], 16, %2;"
                 :: "r"(saddr), "l"(gaddr), "r"(sz) : "memory");
}
__device__ __forceinline__ void cp_commit() {
    asm volatile("cp.async.commit_group;" ::: "memory");
}
template <int N>
__device__ __forceinline__ void cp_wait() {
    asm volatile("cp.async.wait_group %0;" :: "n"(N) : "memory");
}
// NON-volatile: pure register dataflow; lets ptxas interleave with HMMAs.
// __syncthreads() memory clobbers still order these against smem writes.
__device__ __forceinline__ void ldsm4(uint32_t* r, uint32_t addr) {
    asm("ldmatrix.sync.aligned.m8n8.x4.shared.b16 {%0,%1,%2,%3}, [%4];"
        : "=r"(r[0]), "=r"(r[1]), "=r"(r[2]), "=r"(r[3]) : "r"(addr));
}
__device__ __forceinline__ void hmma(float* d, const uint32_t* a, const uint32_t* b) {
    asm("mma.sync.aligned.m16n8k16.row.col.f32.f16.f16.f32 "
        "{%0,%1,%2,%3}, {%4,%5,%6,%7}, {%8,%9}, {%0,%1,%2,%3};"
        : "+f"(d[0]), "+f"(d[1]), "+f"(d[2]), "+f"(d[3])
        : "r"(a[0]), "r"(a[1]), "r"(a[2]), "r"(a[3]), "r"(b[0]), "r"(b[1]));
}

// ---------------- unified prep: weight transposes + rmsnorm + bias concat ----------------
// blocks [0,13824): wtq; [13824,22016): rmsnorm (2 rows each); [22016,22024): biasIR
__global__ __launch_bounds__(256) void prep(
    const float* __restrict__ x, const float* __restrict__ norm_w,
    const float* __restrict__ inp_w, const float* __restrict__ conv_w,
    const float* __restrict__ cl_w, const float* __restrict__ fc1_w,
    const float* __restrict__ res_w, const float* __restrict__ out_w,
    const float* __restrict__ inp_b, const float* __restrict__ res_b,
    __half* __restrict__ xnh, __half* __restrict__ xnl,
    __half* __restrict__ wIR, __half* __restrict__ wCnv,
    __half* __restrict__ wCl, __half* __restrict__ wF1,
    __half* __restrict__ wOut, float* __restrict__ biasIR) {
    __shared__ float tile[32][33];
    __shared__ float sred[2][4];
    int lb = blockIdx.x;
    int tid = threadIdx.x;
    if (lb < 13824) {
        const float* W; __half* T; int Cin, Cout, rowoff, rowtot, base;
        if (lb < 1536)       { W = inp_w;  T = wIR;  Cin = 512;  Cout = 1024; rowoff = 0;    rowtot = 2048; base = 0; }
        else if (lb < 4608)  { W = conv_w; T = wCnv; Cin = 1024; Cout = 1024; rowoff = 0;    rowtot = 1024; base = 1536; }
        else if (lb < 7680)  { W = cl_w;   T = wCl;  Cin = 1024; Cout = 1024; rowoff = 0;    rowtot = 1024; base = 4608; }
        else if (lb < 10752) { W = fc1_w;  T = wF1;  Cin = 1024; Cout = 1024; rowoff = 0;    rowtot = 1024; base = 7680; }
        else if (lb < 12288) { W = res_w;  T = wIR;  Cin = 512;  Cout = 1024; rowoff = 1024; rowtot = 2048; base = 10752; }
        else                 { W = out_w;  T = wOut; Cin = 1024; Cout = 512;  rowoff = 0;    rowtot = 512;  base = 12288; }
        int l = lb - base;
        int nx = Cout / 32;
        int bx = l % nx;
        int rest = l / nx;
        int ny = Cin / 32;
        int by = rest % ny;
        int koff = rest / ny;
        int n0 = bx * 32, c0 = by * 32;
        int tx = tid & 31, ty = tid >> 5;
        const float* Wk = W + (size_t)koff * Cin * Cout;
#pragma unroll
        for (int r = 0; r < 32; r += 8)
            tile[ty + r][tx] = Wk[(size_t)(c0 + ty + r) * Cout + n0 + tx];
        __syncthreads();
        __half* Tk = T + (size_t)koff * rowtot * Cin;
#pragma unroll
        for (int r = 0; r < 32; r += 8)
            Tk[(size_t)(rowoff + n0 + ty + r) * Cin + c0 + tx] =
                __float2half_rn(tile[tx][ty + r]);
    } else if (lb < 22016) {
        int rb = lb - 13824;
        int row = rb * 2 + (tid >> 7);
        int t = tid & 127;
        int sr = tid >> 7;
        const float4* xr = (const float4*)(x + (size_t)row * D1);
        float4 xv = xr[t];
        float ss = xv.x * xv.x + xv.y * xv.y + xv.z * xv.z + xv.w * xv.w;
#pragma unroll
        for (int off = 16; off; off >>= 1)
            ss += __shfl_xor_sync(0xffffffffu, ss, off);
        if ((t & 31) == 0) sred[sr][t >> 5] = ss;
        __syncthreads();
        float tot = sred[sr][0] + sred[sr][1] + sred[sr][2] + sred[sr][3];
        float s = rsqrtf(tot * (1.0f / (float)D1) + 1e-5f);
        float4 wv = ((const float4*)norm_w)[t];
        float o[4];
        o[0] = xv.x * s * wv.x; o[1] = xv.y * s * wv.y;
        o[2] = xv.z * s * wv.z; o[3] = xv.w * s * wv.w;
        size_t base = (size_t)row * D1 + t * 4;
#pragma unroll
        for (int j = 0; j < 4; j += 2) {
            __half h0 = __float2half_rn(o[j]);
            __half h1 = __float2half_rn(o[j + 1]);
            __half2 hp; hp.x = h0; hp.y = h1;
            *(__half2*)(xnh + base + j) = hp;
            __half2 lp;
            lp.x = __float2half_rn(o[j] - __half2float(h0));
            lp.y = __float2half_rn(o[j + 1] - __half2float(h1));
            *(__half2*)(xnl + base + j) = lp;
        }
    } else {
        int i = (lb - 22016) * 256 + tid;
        biasIR[i] = (i < D2) ? inp_b[i] : res_b[i - D2];
    }
}

// ---------------- fp16 conv-GEMM (mma.sync), 2 CTAs/SM, warp tile 32x64 ----------------
// Y[m,n] = act( sum_{koff,c} X[m+koff-1,c] * WT[koff][n][c] + bias[n] )
// X = Xh + Xl (fp16 split), W = fp16. 2 HMMAs per k16.
// kc-major chunk order: ONE 130-row A tile per kc serves all 3 koffs via
// ldsm row offset (+koff). B ring of 4 one-koff slots, A ring of 2 slots.
// Pipeline ordering: wait -> barrier -> issue (issue AFTER barrier so the
// slot being overwritten -- used by iteration cc-1 -- has no live readers).
#define ASTR 80                      // bytes per smem row (32 halfs + 16B pad)
#define A_SLOT (130 * ASTR * 2)      // 20800: hi plane then lo plane (130 rows each)
#define A_PL (130 * ASTR)            // 10400
#define B_BASE (2 * A_SLOT)          // 41600
#define B_SLOT (128 * ASTR)          // 10240
#define GEMM_SMEM (B_BASE + 4 * B_SLOT)  // 82560

// ACT: 0 none, 1 swish, 2 s6 epilogue, 3 dual (plain->Y / swish->Y2, stride D2).
// OUTF: 0 split fp16, 1 fp32.
template <int ACT, int OUTF>
__global__ __launch_bounds__(256, 2) void mm_h(
    const __half* __restrict__ Ah, const __half* __restrict__ Al,
    const __half* __restrict__ Wt,
    const float* __restrict__ bias, int Cin, int Cout, int M,
    __half* __restrict__ Yh, __half* __restrict__ Yl, float* __restrict__ Yf,
    __half* __restrict__ Y2h, __half* __restrict__ Y2l,
    const __half* __restrict__ xch, const __half* __restrict__ xcl,
    const __half* __restrict__ xrh, const __half* __restrict__ xrl,
    const float* __restrict__ cbv) {
    extern __shared__ char smem[];
    const uint32_t sb = s2u(smem);
    const int tid = threadIdx.x;
    const int wid = tid >> 5;
    const int lane = tid & 31;
    const int warp_m = wid >> 1;   // 0..3 (32 rows each)
    const int warp_n = wid & 1;    // 0..1 (64 cols each)
    const int bm = blockIdx.y * 128;
    const int bn = blockIdx.x * 128;
    const int KC = Cin >> 5;       // 32-wide k chunks per tap
    const int nch = 3 * KC;        // cc = kc*3 + koff

    float acc[2][8][4];
#pragma unroll
    for (int i = 0; i < 2; i++)
#pragma unroll
        for (int j = 0; j < 8; j++)
#pragma unroll
            for (int q = 0; q < 4; q++) acc[i][j][q] = 0.f;

    // A loader: thread t < 130 loads tile row t (= input row bm-1+t), 64B/plane.
    // Row 0 is only consumed via koff=0 by output bm; row 129 only via koff=2
    // by output bm+127 -> zero them exactly at batch boundaries.
    const bool a_active = tid < 130;
    bool a_valid = true;
    long long a_grow = (long long)bm - 1 + tid;
    if (tid == 0 && (bm & LMASK) == 0) a_valid = false;
    if (tid == 129 && ((bm + 128) & LMASK) == 0) a_valid = false;
    if (a_grow < 0) a_grow = 0;
    if (a_grow >= M) a_grow = M - 1;
    const uint32_t a_sz = a_valid ? 16u : 0u;

    auto issueA = [&](int kc) {
        if (!a_active) return;
        uint32_t dst = sb + (uint32_t)(kc & 1) * A_SLOT + (uint32_t)tid * ASTR;
        const __half* ph = Ah + a_grow * Cin + kc * 32;
        const __half* pl = Al + a_grow * Cin + kc * 32;
#pragma unroll
        for (int i = 0; i < 4; i++) {
            cp16(dst + i * 16, ph + i * 8, a_sz);
            cp16(dst + A_PL + i * 16, pl + i * 8, a_sz);
        }
    };

    // B loader: 2 threads per row, 32B each; one koff tile per cc.
    const int blr = tid >> 1;
    const int blseg = tid & 1;
    auto issueB = [&](int cc) {
        int koff = cc % 3;
        int kc = cc / 3;
        uint32_t dst = sb + B_BASE + (uint32_t)(cc & 3) * B_SLOT +
                       (uint32_t)blr * ASTR + (uint32_t)blseg * 32;
        size_t bo = ((size_t)koff * Cout + bn + blr) * Cin + kc * 32 + blseg * 16;
        cp16(dst, Wt + bo, 16u);
        cp16(dst + 16, Wt + bo + 8, 16u);
    };

    // prologue: groups g0={A0,B0}, g1={B1}, g2={B2}
    issueA(0); issueB(0); cp_commit();
    issueB(1); cp_commit();
    issueB(2); cp_commit();

    // ldmatrix address components
    const int a_row = warp_m * 32 + (lane & 15);   // local output row (frag)
    const uint32_t a_kb = (uint32_t)(lane >> 4) * 16;
    const int mi = lane >> 3;
    const int b_row = warp_n * 64 + ((mi >> 1) << 3) + (lane & 7);
    const uint32_t b_kb = (uint32_t)(mi & 1) * 16;

    for (int cc = 0; cc < nch; cc++) {
        // At iteration start, groups issued = min(cc+3, nch); group cc must be
        // complete before compute.
        int rem = nch - 1 - cc;
        if (rem >= 2) cp_wait<2>();
        else if (rem == 1) cp_wait<1>();
        else cp_wait<0>();
        __syncthreads();
        // Issue AFTER the barrier: slot (cc+3)&3 == (cc-1)&3 was last read by
        // iteration cc-1, and every warp finished that before this barrier.
        if (cc + 3 < nch) {
            int nx = cc + 3;
            issueB(nx);
            if (nx % 3 == 0) issueA(nx / 3);
            cp_commit();
        }

        const int koff = cc % 3;
        const int kc = cc / 3;
        const uint32_t abase = sb + (uint32_t)(kc & 1) * A_SLOT;
        const uint32_t bbase = sb + B_BASE + (uint32_t)(cc & 3) * B_SLOT;

#pragma unroll
        for (int k16 = 0; k16 < 2; k16++) {
            uint32_t ah[2][4], al[2][4];
#pragma unroll
            for (int mt = 0; mt < 2; mt++) {
                uint32_t addr = abase +
                                (uint32_t)(a_row + mt * 16 + koff) * ASTR +
                                (uint32_t)k16 * 32 + a_kb;
                ldsm4(ah[mt], addr);
                ldsm4(al[mt], addr + A_PL);
            }
            uint32_t bf[8][2];
#pragma unroll
            for (int p = 0; p < 4; p++) {
                uint32_t addr = bbase + (uint32_t)(b_row + p * 16) * ASTR +
                                (uint32_t)k16 * 32 + b_kb;
                uint32_t t4[4];
                ldsm4(t4, addr);
                bf[2 * p][0] = t4[0]; bf[2 * p][1] = t4[1];
                bf[2 * p + 1][0] = t4[2]; bf[2 * p + 1][1] = t4[3];
            }
#pragma unroll
            for (int mt = 0; mt < 2; mt++)
#pragma unroll
                for (int nt = 0; nt < 8; nt++)
                    hmma(acc[mt][nt], ah[mt], bf[nt]);
#pragma unroll
            for (int mt = 0; mt < 2; mt++)
#pragma unroll
                for (int nt = 0; nt < 8; nt++)
                    hmma(acc[mt][nt], al[mt], bf[nt]);
        }
    }

    // ---------------- epilogue ----------------
    const int erow0 = bm + warp_m * 32 + (lane >> 2);
    const int ecol0 = bn + warp_n * 64 + (lane & 3) * 2;
    const bool isres = (ACT == 3) && (bn >= D2);
    const __half* obh = (ACT == 3) ? (isres ? Y2h : Yh) : Yh;
    const __half* obl = (ACT == 3) ? (isres ? Y2l : Yl) : Yl;
    const int coff = isres ? D2 : 0;
    const int ostride = (ACT == 3) ? D2 : Cout;
#pragma unroll
    for (int mt = 0; mt < 2; mt++) {
#pragma unroll
        for (int h = 0; h < 2; h++) {
            int row = erow0 + mt * 16 + h * 8;
            float cbs = 0.f;
            if (ACT == 2) cbs = cbv[row];
            size_t yb = (size_t)row * ostride;
#pragma unroll
            for (int nt = 0; nt < 8; nt++) {
                int col = ecol0 + nt * 8;
                float v0 = acc[mt][nt][2 * h + 0] + bias[col];
                float v1 = acc[mt][nt][2 * h + 1] + bias[col + 1];
                if (ACT == 1) { v0 = swish_f(v0); v1 = swish_f(v1); }
                if (ACT == 3 && isres) { v0 = swish_f(v0); v1 = swish_f(v1); }
                if (ACT == 2) {
                    size_t o = yb + col;
                    __half2 ch = *(const __half2*)(xch + o);
                    __half2 cl = *(const __half2*)(xcl + o);
                    __half2 rh = *(const __half2*)(xrh + o);
                    __half2 rl = *(const __half2*)(xrl + o);
                    float xc0 = __half2float(ch.x) + __half2float(cl.x);
                    float xc1 = __half2float(ch.y) + __half2float(cl.y);
                    float xr0 = __half2float(rh.x) + __half2float(rl.x);
                    float xr1 = __half2float(rh.y) + __half2float(rl.y);
                    v0 = xc0 * softplus_f(v0) * cbs * xr0;
                    v1 = xc1 * softplus_f(v1) * cbs * xr1;
                }
                if (OUTF == 0) {
                    size_t o = yb + col - coff;
                    __half h0 = __float2half_rn(v0);
                    __half h1 = __float2half_rn(v1);
                    __half2 hp; hp.x = h0; hp.y = h1;
                    *(__half2*)((__half*)obh + o) = hp;
                    __half2 lp;
                    lp.x = __float2half_rn(v0 - __half2float(h0));
                    lp.y = __float2half_rn(v1 - __half2float(h1));
                    *(__half2*)((__half*)obl + o) = lp;
                } else {
                    *(float2*)(Yf + yb + col) = make_float2(v0, v1);
                }
            }
        }
    }
}

// ---------------- bc: cb[m] = sum_n (conv16(fc2)+b2)*(conv16(fc3)+b3) ----------------
#define BC_SMEM (2 * 3 * D2 * NS * 2)   // 196608 bytes
__global__ __launch_bounds__(256, 1) void bc2(
    const __half* __restrict__ Xh, const __half* __restrict__ Xl,
    const float* __restrict__ w2, const float* __restrict__ b2,
    const float* __restrict__ w3, const float* __restrict__ b3,
    float* __restrict__ cbout, int M) {
    extern __shared__ __half ws[];
    __half* w2s = ws;
    __half* w3s = ws + 3 * D2 * NS;
    const int tid = threadIdx.x;
    const int wid = tid >> 5;
    const int lane = tid & 31;
    const int bm = blockIdx.x * 128;

    for (int i = tid; i < 3 * D2 * NS; i += 256) {
        w2s[i] = __float2half_rn(w2[i]);
        w3s[i] = __float2half_rn(w3[i]);
    }
    __syncthreads();

    for (int g = 0; g < 4; g++) {
        int r0 = bm + wid * 16 + g * 4;
        float accB[4][NS], accC[4][NS];
#pragma unroll
        for (int j = 0; j < 4; j++)
#pragma unroll
            for (int n = 0; n < NS; n++) { accB[j][n] = 0.f; accC[j][n] = 0.f; }

        for (int koff = 0; koff < 3; koff++) {
            const __half* xh0 = Xh + (size_t)(r0 + koff - 1) * D2;
            const __half* xl0 = Xl + (size_t)(r0 + koff - 1) * D2;
            bool val[4];
#pragma unroll
            for (int j = 0; j < 4; j++) {
                int pos = (r0 + j) & LMASK;
                val[j] = !((koff == 0 && pos == 0) || (koff == 2 && pos == LMASK));
            }
            const __half* w2k = w2s + koff * D2 * NS;
            const __half* w3k = w3s + koff * D2 * NS;
            for (int kk = lane; kk < D2; kk += 32) {
                float xv[4];
#pragma unroll
                for (int j = 0; j < 4; j++) {
                    size_t o = (size_t)j * D2 + kk;
                    xv[j] = val[j] ? (__half2float(xh0[o]) + __half2float(xl0[o]))
                                   : 0.f;
                }
                const __half2* wb = (const __half2*)(w2k + kk * NS);
                const __half2* wc = (const __half2*)(w3k + kk * NS);
#pragma unroll
                for (int q = 0; q < 8; q++) {
                    float2 fb = __half22float2(wb[q]);
                    float2 fc = __half22float2(wc[q]);
#pragma unroll
                    for (int j = 0; j < 4; j++) {
                        accB[j][2 * q] += xv[j] * fb.x;
                        accB[j][2 * q + 1] += xv[j] * fb.y;
                        accC[j][2 * q] += xv[j] * fc.x;
                        accC[j][2 * q + 1] += xv[j] * fc.y;
                    }
                }
            }
        }
#pragma unroll
        for (int j = 0; j < 4; j++) {
#pragma unroll
            for (int n = 0; n < NS; n++) {
#pragma unroll
                for (int off = 16; off; off >>= 1) {
                    accB[j][n] += __shfl_xor_sync(0xffffffffu, accB[j][n], off);
                    accC[j][n] += __shfl_xor_sync(0xffffffffu, accC[j][n], off);
                }
            }
            if (lane == 0) {
                float s = 0.f;
#pragma unroll
                for (int n = 0; n < NS; n++)
                    s += (accB[j][n] + b2[n]) * (accC[j][n] + b3[n]);
                cbout[r0 + j] = s;
            }
        }
    }
}

// ---------------- launch ----------------
extern "C" void kernel_launch(void* const* d_in, const int* in_sizes, int n_in,
                              void* d_out, int out_size) {
    const float* x      = (const float*)d_in[0];
    const float* norm_w = (const float*)d_in[1];
    const float* inp_w  = (const float*)d_in[2];
    const float* inp_b  = (const float*)d_in[3];
    const float* conv_w = (const float*)d_in[4];
    const float* conv_b = (const float*)d_in[5];
    const float* cl_w   = (const float*)d_in[6];
    const float* cl_b   = (const float*)d_in[7];
    const float* fc1_w  = (const float*)d_in[8];
    const float* fc1_b  = (const float*)d_in[9];
    const float* fc2_w  = (const float*)d_in[10];
    const float* fc2_b  = (const float*)d_in[11];
    const float* fc3_w  = (const float*)d_in[12];
    const float* fc3_b  = (const float*)d_in[13];
    // d_in[14] = A (mathematically dead)
    const float* res_w  = (const float*)d_in[15];
    const float* res_b  = (const float*)d_in[16];
    const float* out_w  = (const float*)d_in[17];
    const float* out_b  = (const float*)d_in[18];

    int M = in_sizes[0] / D1;  // 16384

    __half *xnh, *xnl, *t0h, *t0l, *t1h, *t1l, *t2h, *t2l, *t3h, *t3l;
    __half *wIR, *wCnv, *wCl, *wF1, *wOut;
    float *cb, *biasIR;
    cudaGetSymbolAddress((void**)&xnh, g_xnh);
    cudaGetSymbolAddress((void**)&xnl, g_xnl);
    cudaGetSymbolAddress((void**)&t0h, g_t0h);
    cudaGetSymbolAddress((void**)&t0l, g_t0l);
    cudaGetSymbolAddress((void**)&t1h, g_t1h);
    cudaGetSymbolAddress((void**)&t1l, g_t1l);
    cudaGetSymbolAddress((void**)&t2h, g_t2h);
    cudaGetSymbolAddress((void**)&t2l, g_t2l);
    cudaGetSymbolAddress((void**)&t3h, g_t3h);
    cudaGetSymbolAddress((void**)&t3l, g_t3l);
    cudaGetSymbolAddress((void**)&cb, g_cb);
    cudaGetSymbolAddress((void**)&wIR, g_wIR);
    cudaGetSymbolAddress((void**)&wCnv, g_wCnv);
    cudaGetSymbolAddress((void**)&wCl, g_wCl);
    cudaGetSymbolAddress((void**)&wF1, g_wF1);
    cudaGetSymbolAddress((void**)&wOut, g_wOut);
    cudaGetSymbolAddress((void**)&biasIR, g_biasIR);

    cudaFuncSetAttribute(mm_h<0, 0>, cudaFuncAttributeMaxDynamicSharedMemorySize, GEMM_SMEM);
    cudaFuncSetAttribute(mm_h<1, 0>, cudaFuncAttributeMaxDynamicSharedMemorySize, GEMM_SMEM);
    cudaFuncSetAttribute(mm_h<2, 0>, cudaFuncAttributeMaxDynamicSharedMemorySize, GEMM_SMEM);
    cudaFuncSetAttribute(mm_h<3, 0>, cudaFuncAttributeMaxDynamicSharedMemorySize, GEMM_SMEM);
    cudaFuncSetAttribute(mm_h<0, 1>, cudaFuncAttributeMaxDynamicSharedMemorySize, GEMM_SMEM);
    cudaFuncSetAttribute(bc2, cudaFuncAttributeMaxDynamicSharedMemorySize, BC_SMEM);

    // 1) prep: all weight transposes + rmsnorm + bias concat (one launch)
    prep<<<22024, 256>>>(x, norm_w, inp_w, conv_w, cl_w, fc1_w, res_w, out_w,
                         inp_b, res_b, xnh, xnl, wIR, wCnv, wCl, wF1, wOut, biasIR);

    dim3 blk(256);
    dim3 g_fuse(2048 / 128, M / 128);  // 16 x 128
    dim3 g_big(D2 / 128, M / 128);     // 8 x 128
    dim3 g_out(D1 / 128, M / 128);     // 4 x 128

    // 2) fused: t0 = conv(xn, inp) [cols 0-1023]; t3 = swish(conv(xn, res)) [cols 1024-2047]
    mm_h<3, 0><<<g_fuse, blk, GEMM_SMEM>>>(xnh, xnl, wIR, biasIR, D1, 2048, M,
        t0h, t0l, nullptr, t3h, t3l, nullptr, nullptr, nullptr, nullptr, nullptr);
    // 3) t1 = swish(conv(t0, conv))
    mm_h<1, 0><<<g_big, blk, GEMM_SMEM>>>(t0h, t0l, wCnv, conv_b, D2, D2, M,
        t1h, t1l, nullptr, nullptr, nullptr, nullptr, nullptr, nullptr, nullptr, nullptr);
    // 4) t2 = conv(t1, cl) = x_conv_out
    mm_h<0, 0><<<g_big, blk, GEMM_SMEM>>>(t1h, t1l, wCl, cl_b, D2, D2, M,
        t2h, t2l, nullptr, nullptr, nullptr, nullptr, nullptr, nullptr, nullptr, nullptr);
    // 5) cb[m]
    bc2<<<M / 128, 256, BC_SMEM>>>(t2h, t2l, fc2_w, fc2_b, fc3_w, fc3_b, cb, M);
    // 6) t0 = x_ssm * x_res (s6 epilogue; xc = t2, xr = t3)
    mm_h<2, 0><<<g_big, blk, GEMM_SMEM>>>(t2h, t2l, wF1, fc1_b, D2, D2, M,
        t0h, t0l, nullptr, nullptr, nullptr, t2h, t2l, t3h, t3l, cb);
    // 7) out = conv(t0, out) -> fp32 d_out
    mm_h<0, 1><<<g_out, blk, GEMM_SMEM>>>(t0h, t0l, wOut, out_b, D2, D1, M,
        nullptr, nullptr, (float*)d_out, nullptr, nullptr, nullptr, nullptr, nullptr, nullptr, nullptr);
}

// round 14
// speedup vs baseline: 1.0946x; 1.0673x over previous
#include <cuda_runtime.h>
#include <cuda_fp16.h>
#include <math.h>
#include <cstdint>

#define D1 512
#define D2 1024
#define NS 16
#define MTOT 16384
#define LMASK 4095

// ---------------- scratch (static device globals; no allocation) ----------------
__device__ __half g_xnh[(size_t)MTOT * D1], g_xnl[(size_t)MTOT * D1];
__device__ __half g_t0h[(size_t)MTOT * D2], g_t0l[(size_t)MTOT * D2];
__device__ __half g_t1h[(size_t)MTOT * D2], g_t1l[(size_t)MTOT * D2];
__device__ __half g_t2h[(size_t)MTOT * D2], g_t2l[(size_t)MTOT * D2];
__device__ __half g_t3h[(size_t)MTOT * D2], g_t3l[(size_t)MTOT * D2];
__device__ float g_cb[MTOT];
// transposed fp16 weights
__device__ __half g_wIR[3 * 2048 * D1];     // inp rows 0-1023, res rows 1024-2047
__device__ __half g_wCnv[3 * D2 * D2];
__device__ __half g_wCl[3 * D2 * D2];
__device__ __half g_wF1[3 * D2 * D2];
__device__ __half g_wOut[3 * D1 * D2];      // [koff][512][1024]
__device__ __half g_wBC[3 * 32 * D2];       // [koff][n<16:fc2 | n>=16:fc3][1024]
__device__ float g_biasIR[2048];

// ---------------- small math ----------------
__device__ __forceinline__ float softplus_f(float x) {
    return (x > 20.0f) ? x : log1pf(expf(x));
}
__device__ __forceinline__ float swish_f(float x) {
    return x / (1.0f + expf(-x));
}

// ---------------- ptx helpers ----------------
__device__ __forceinline__ uint32_t s2u(const void* p) {
    uint32_t a;
    asm("{ .reg .u64 t; cvta.to.shared.u64 t, %1; cvt.u32.u64 %0, t; }"
        : "=r"(a) : "l"(p));
    return a;
}
__device__ __forceinline__ void cp16(uint32_t saddr, const void* gaddr, uint32_t sz) {
    asm volatile("cp.async.cg.shared.global [%0], [%1], 16, %2;"
                 :: "r"(saddr), "l"(gaddr), "r"(sz) : "memory");
}
__device__ __forceinline__ void cp_commit() {
    asm volatile("cp.async.commit_group;" ::: "memory");
}
template <int N>
__device__ __forceinline__ void cp_wait() {
    asm volatile("cp.async.wait_group %0;" :: "n"(N) : "memory");
}
__device__ __forceinline__ void ldsm4(uint32_t* r, uint32_t addr) {
    asm("ldmatrix.sync.aligned.m8n8.x4.shared.b16 {%0,%1,%2,%3}, [%4];"
        : "=r"(r[0]), "=r"(r[1]), "=r"(r[2]), "=r"(r[3]) : "r"(addr));
}
__device__ __forceinline__ void hmma(float* d, const uint32_t* a, const uint32_t* b) {
    asm("mma.sync.aligned.m16n8k16.row.col.f32.f16.f16.f32 "
        "{%0,%1,%2,%3}, {%4,%5,%6,%7}, {%8,%9}, {%0,%1,%2,%3};"
        : "+f"(d[0]), "+f"(d[1]), "+f"(d[2]), "+f"(d[3])
        : "r"(a[0]), "r"(a[1]), "r"(a[2]), "r"(a[3]), "r"(b[0]), "r"(b[1]));
}

// ---------------- unified prep ----------------
// [0,13824): big weight transposes; [13824,22016): rmsnorm (2 rows each);
// [22016,22024): biasIR; [22024,22216): fc2/fc3 -> wBC transpose
__global__ __launch_bounds__(256) void prep(
    const float* __restrict__ x, const float* __restrict__ norm_w,
    const float* __restrict__ inp_w, const float* __restrict__ conv_w,
    const float* __restrict__ cl_w, const float* __restrict__ fc1_w,
    const float* __restrict__ res_w, const float* __restrict__ out_w,
    const float* __restrict__ fc2_w, const float* __restrict__ fc3_w,
    const float* __restrict__ inp_b, const float* __restrict__ res_b,
    __half* __restrict__ xnh, __half* __restrict__ xnl,
    __half* __restrict__ wIR, __half* __restrict__ wCnv,
    __half* __restrict__ wCl, __half* __restrict__ wF1,
    __half* __restrict__ wOut, __half* __restrict__ wBC,
    float* __restrict__ biasIR) {
    __shared__ float tile[32][33];
    __shared__ float sred[2][4];
    int lb = blockIdx.x;
    int tid = threadIdx.x;
    if (lb < 13824) {
        const float* W; __half* T; int Cin, Cout, rowoff, rowtot, base;
        if (lb < 1536)       { W = inp_w;  T = wIR;  Cin = 512;  Cout = 1024; rowoff = 0;    rowtot = 2048; base = 0; }
        else if (lb < 4608)  { W = conv_w; T = wCnv; Cin = 1024; Cout = 1024; rowoff = 0;    rowtot = 1024; base = 1536; }
        else if (lb < 7680)  { W = cl_w;   T = wCl;  Cin = 1024; Cout = 1024; rowoff = 0;    rowtot = 1024; base = 4608; }
        else if (lb < 10752) { W = fc1_w;  T = wF1;  Cin = 1024; Cout = 1024; rowoff = 0;    rowtot = 1024; base = 7680; }
        else if (lb < 12288) { W = res_w;  T = wIR;  Cin = 512;  Cout = 1024; rowoff = 1024; rowtot = 2048; base = 10752; }
        else                 { W = out_w;  T = wOut; Cin = 1024; Cout = 512;  rowoff = 0;    rowtot = 512;  base = 12288; }
        int l = lb - base;
        int nx = Cout / 32;
        int bx = l % nx;
        int rest = l / nx;
        int ny = Cin / 32;
        int by = rest % ny;
        int koff = rest / ny;
        int n0 = bx * 32, c0 = by * 32;
        int tx = tid & 31, ty = tid >> 5;
        const float* Wk = W + (size_t)koff * Cin * Cout;
#pragma unroll
        for (int r = 0; r < 32; r += 8)
            tile[ty + r][tx] = Wk[(size_t)(c0 + ty + r) * Cout + n0 + tx];
        __syncthreads();
        __half* Tk = T + (size_t)koff * rowtot * Cin;
#pragma unroll
        for (int r = 0; r < 32; r += 8)
            Tk[(size_t)(rowoff + n0 + ty + r) * Cin + c0 + tx] =
                __float2half_rn(tile[tx][ty + r]);
    } else if (lb < 22016) {
        int rb = lb - 13824;
        int row = rb * 2 + (tid >> 7);
        int t = tid & 127;
        int sr = tid >> 7;
        const float4* xr = (const float4*)(x + (size_t)row * D1);
        float4 xv = xr[t];
        float ss = xv.x * xv.x + xv.y * xv.y + xv.z * xv.z + xv.w * xv.w;
#pragma unroll
        for (int off = 16; off; off >>= 1)
            ss += __shfl_xor_sync(0xffffffffu, ss, off);
        if ((t & 31) == 0) sred[sr][t >> 5] = ss;
        __syncthreads();
        float tot = sred[sr][0] + sred[sr][1] + sred[sr][2] + sred[sr][3];
        float s = rsqrtf(tot * (1.0f / (float)D1) + 1e-5f);
        float4 wv = ((const float4*)norm_w)[t];
        float o[4];
        o[0] = xv.x * s * wv.x; o[1] = xv.y * s * wv.y;
        o[2] = xv.z * s * wv.z; o[3] = xv.w * s * wv.w;
        size_t base = (size_t)row * D1 + t * 4;
#pragma unroll
        for (int j = 0; j < 4; j += 2) {
            __half h0 = __float2half_rn(o[j]);
            __half h1 = __float2half_rn(o[j + 1]);
            __half2 hp; hp.x = h0; hp.y = h1;
            *(__half2*)(xnh + base + j) = hp;
            __half2 lp;
            lp.x = __float2half_rn(o[j] - __half2float(h0));
            lp.y = __float2half_rn(o[j + 1] - __half2float(h1));
            *(__half2*)(xnl + base + j) = lp;
        }
    } else if (lb < 22024) {
        int i = (lb - 22016) * 256 + tid;
        biasIR[i] = (i < D2) ? inp_b[i] : res_b[i - D2];
    } else {
        // fc2/fc3 transpose: W[koff][1024][16] -> wBC[koff][n(+16)][1024]
        int idx = lb - 22024;            // 0..191
        int tensor = idx & 1;            // 0=fc2, 1=fc3
        int rest = idx >> 1;             // 0..95
        int koff = rest >> 5;            // 0..2
        int c0 = (rest & 31) * 32;       // cin block
        const float* W = tensor ? fc3_w : fc2_w;
        const float* Wk = W + (size_t)koff * D2 * NS;
        __half* Tk = wBC + (size_t)koff * 32 * D2;
#pragma unroll
        for (int j = 0; j < 2; j++) {
            int e = tid + j * 256;       // 0..511
            int ci = e >> 4;             // 0..31
            int n = e & 15;
            Tk[(size_t)(n + 16 * tensor) * D2 + c0 + ci] =
                __float2half_rn(Wk[(size_t)(c0 + ci) * NS + n]);
        }
    }
}

// ---------------- fp16 conv-GEMM (mma.sync), 2 CTAs/SM, warp tile 32x64 ----------------
// Y[m,n] = act( sum_{koff,c} X[m+koff-1,c] * WT[koff][n][c] + bias[n] )
// X = Xh + Xl (fp16 split), W = fp16. 2 HMMAs per k16.
// kc-major chunk order: ONE 130-row A tile per kc serves all 3 koffs via
// ldsm row offset (+koff). B ring of 4 one-koff slots, A ring of 2 slots.
#define ASTR 80                      // bytes per smem row (32 halfs + 16B pad)
#define A_SLOT (130 * ASTR * 2)      // 20800: hi plane then lo plane
#define A_PL (130 * ASTR)            // 10400
#define B_BASE (2 * A_SLOT)          // 41600
#define B_SLOT (128 * ASTR)          // 10240
#define GEMM_SMEM (B_BASE + 4 * B_SLOT)  // 82560

// ACT: 0 none, 1 swish, 2 s6 epilogue, 3 dual (plain->Y / swish->Y2, stride D2).
// OUTF: 0 split fp16, 1 fp32.
template <int ACT, int OUTF>
__global__ __launch_bounds__(256, 2) void mm_h(
    const __half* __restrict__ Ah, const __half* __restrict__ Al,
    const __half* __restrict__ Wt,
    const float* __restrict__ bias, int Cin, int Cout, int M,
    __half* __restrict__ Yh, __half* __restrict__ Yl, float* __restrict__ Yf,
    __half* __restrict__ Y2h, __half* __restrict__ Y2l,
    const __half* __restrict__ xch, const __half* __restrict__ xcl,
    const __half* __restrict__ xrh, const __half* __restrict__ xrl,
    const float* __restrict__ cbv) {
    extern __shared__ char smem[];
    const uint32_t sb = s2u(smem);
    const int tid = threadIdx.x;
    const int wid = tid >> 5;
    const int lane = tid & 31;
    const int warp_m = wid >> 1;   // 0..3 (32 rows each)
    const int warp_n = wid & 1;    // 0..1 (64 cols each)
    const int bm = blockIdx.y * 128;
    const int bn = blockIdx.x * 128;
    const int KC = Cin >> 5;
    const int nch = 3 * KC;        // cc = kc*3 + koff

    float acc[2][8][4];
#pragma unroll
    for (int i = 0; i < 2; i++)
#pragma unroll
        for (int j = 0; j < 8; j++)
#pragma unroll
            for (int q = 0; q < 4; q++) acc[i][j][q] = 0.f;

    const bool a_active = tid < 130;
    bool a_valid = true;
    long long a_grow = (long long)bm - 1 + tid;
    if (tid == 0 && (bm & LMASK) == 0) a_valid = false;
    if (tid == 129 && ((bm + 128) & LMASK) == 0) a_valid = false;
    if (a_grow < 0) a_grow = 0;
    if (a_grow >= M) a_grow = M - 1;
    const uint32_t a_sz = a_valid ? 16u : 0u;

    auto issueA = [&](int kc) {
        if (!a_active) return;
        uint32_t dst = sb + (uint32_t)(kc & 1) * A_SLOT + (uint32_t)tid * ASTR;
        const __half* ph = Ah + a_grow * Cin + kc * 32;
        const __half* pl = Al + a_grow * Cin + kc * 32;
#pragma unroll
        for (int i = 0; i < 4; i++) {
            cp16(dst + i * 16, ph + i * 8, a_sz);
            cp16(dst + A_PL + i * 16, pl + i * 8, a_sz);
        }
    };

    const int blr = tid >> 1;
    const int blseg = tid & 1;
    auto issueB = [&](int cc) {
        int koff = cc % 3;
        int kc = cc / 3;
        uint32_t dst = sb + B_BASE + (uint32_t)(cc & 3) * B_SLOT +
                       (uint32_t)blr * ASTR + (uint32_t)blseg * 32;
        size_t bo = ((size_t)koff * Cout + bn + blr) * Cin + kc * 32 + blseg * 16;
        cp16(dst, Wt + bo, 16u);
        cp16(dst + 16, Wt + bo + 8, 16u);
    };

    issueA(0); issueB(0); cp_commit();
    issueB(1); cp_commit();
    issueB(2); cp_commit();

    const int a_row = warp_m * 32 + (lane & 15);
    const uint32_t a_kb = (uint32_t)(lane >> 4) * 16;
    const int mi = lane >> 3;
    const int b_row = warp_n * 64 + ((mi >> 1) << 3) + (lane & 7);
    const uint32_t b_kb = (uint32_t)(mi & 1) * 16;

    for (int cc = 0; cc < nch; cc++) {
        int rem = nch - 1 - cc;
        if (rem >= 2) cp_wait<2>();
        else if (rem == 1) cp_wait<1>();
        else cp_wait<0>();
        __syncthreads();
        if (cc + 3 < nch) {
            int nx = cc + 3;
            issueB(nx);
            if (nx % 3 == 0) issueA(nx / 3);
            cp_commit();
        }

        const int koff = cc % 3;
        const int kc = cc / 3;
        const uint32_t abase = sb + (uint32_t)(kc & 1) * A_SLOT;
        const uint32_t bbase = sb + B_BASE + (uint32_t)(cc & 3) * B_SLOT;

#pragma unroll
        for (int k16 = 0; k16 < 2; k16++) {
            uint32_t ah[2][4], al[2][4];
#pragma unroll
            for (int mt = 0; mt < 2; mt++) {
                uint32_t addr = abase +
                                (uint32_t)(a_row + mt * 16 + koff) * ASTR +
                                (uint32_t)k16 * 32 + a_kb;
                ldsm4(ah[mt], addr);
                ldsm4(al[mt], addr + A_PL);
            }
            uint32_t bf[8][2];
#pragma unroll
            for (int p = 0; p < 4; p++) {
                uint32_t addr = bbase + (uint32_t)(b_row + p * 16) * ASTR +
                                (uint32_t)k16 * 32 + b_kb;
                uint32_t t4[4];
                ldsm4(t4, addr);
                bf[2 * p][0] = t4[0]; bf[2 * p][1] = t4[1];
                bf[2 * p + 1][0] = t4[2]; bf[2 * p + 1][1] = t4[3];
            }
#pragma unroll
            for (int mt = 0; mt < 2; mt++)
#pragma unroll
                for (int nt = 0; nt < 8; nt++)
                    hmma(acc[mt][nt], ah[mt], bf[nt]);
#pragma unroll
            for (int mt = 0; mt < 2; mt++)
#pragma unroll
                for (int nt = 0; nt < 8; nt++)
                    hmma(acc[mt][nt], al[mt], bf[nt]);
        }
    }

    // ---------------- epilogue ----------------
    const int erow0 = bm + warp_m * 32 + (lane >> 2);
    const int ecol0 = bn + warp_n * 64 + (lane & 3) * 2;
    const bool isres = (ACT == 3) && (bn >= D2);
    const __half* obh = (ACT == 3) ? (isres ? Y2h : Yh) : Yh;
    const __half* obl = (ACT == 3) ? (isres ? Y2l : Yl) : Yl;
    const int coff = isres ? D2 : 0;
    const int ostride = (ACT == 3) ? D2 : Cout;
#pragma unroll
    for (int mt = 0; mt < 2; mt++) {
#pragma unroll
        for (int h = 0; h < 2; h++) {
            int row = erow0 + mt * 16 + h * 8;
            float cbs = 0.f;
            if (ACT == 2) cbs = cbv[row];
            size_t yb = (size_t)row * ostride;
#pragma unroll
            for (int nt = 0; nt < 8; nt++) {
                int col = ecol0 + nt * 8;
                float v0 = acc[mt][nt][2 * h + 0] + bias[col];
                float v1 = acc[mt][nt][2 * h + 1] + bias[col + 1];
                if (ACT == 1) { v0 = swish_f(v0); v1 = swish_f(v1); }
                if (ACT == 3 && isres) { v0 = swish_f(v0); v1 = swish_f(v1); }
                if (ACT == 2) {
                    size_t o = yb + col;
                    __half2 ch = *(const __half2*)(xch + o);
                    __half2 cl = *(const __half2*)(xcl + o);
                    __half2 rh = *(const __half2*)(xrh + o);
                    __half2 rl = *(const __half2*)(xrl + o);
                    float xc0 = __half2float(ch.x) + __half2float(cl.x);
                    float xc1 = __half2float(ch.y) + __half2float(cl.y);
                    float xr0 = __half2float(rh.x) + __half2float(rl.x);
                    float xr1 = __half2float(rh.y) + __half2float(rl.y);
                    v0 = xc0 * softplus_f(v0) * cbs * xr0;
                    v1 = xc1 * softplus_f(v1) * cbs * xr1;
                }
                if (OUTF == 0) {
                    size_t o = yb + col - coff;
                    __half h0 = __float2half_rn(v0);
                    __half h1 = __float2half_rn(v1);
                    __half2 hp; hp.x = h0; hp.y = h1;
                    *(__half2*)((__half*)obh + o) = hp;
                    __half2 lp;
                    lp.x = __float2half_rn(v0 - __half2float(h0));
                    lp.y = __float2half_rn(v1 - __half2float(h1));
                    *(__half2*)((__half*)obl + o) = lp;
                } else {
                    *(float2*)(Yf + yb + col) = make_float2(v0, v1);
                }
            }
        }
    }
}

// ---------------- bcg: cb via skinny HMMA GEMM (N=32 = fc2||fc3) ----------------
// P[m, 0..15] = Bm, P[m, 16..31] = Cm; cb[m] = sum_n (Bm+b2)(Cm+b3).
// Same pipeline skeleton as mm_h; 8 warps x 16-row warp tiles, all N=32.
#define BCG_B_SLOT (32 * ASTR)              // 2560
#define BCG_SMEM (B_BASE + 4 * BCG_B_SLOT)  // 51840

__global__ __launch_bounds__(256, 2) void bcg(
    const __half* __restrict__ Ah, const __half* __restrict__ Al,
    const __half* __restrict__ Wbc,
    const float* __restrict__ b2, const float* __restrict__ b3,
    float* __restrict__ cbout, int M) {
    extern __shared__ char smem[];
    const uint32_t sb = s2u(smem);
    const int tid = threadIdx.x;
    const int wid = tid >> 5;
    const int lane = tid & 31;
    const int bm = blockIdx.x * 128;
    const int KC = D2 >> 5;        // 32
    const int nch = 3 * KC;        // 96

    float acc[4][4];
#pragma unroll
    for (int j = 0; j < 4; j++)
#pragma unroll
        for (int q = 0; q < 4; q++) acc[j][q] = 0.f;

    const bool a_active = tid < 130;
    bool a_valid = true;
    long long a_grow = (long long)bm - 1 + tid;
    if (tid == 0 && (bm & LMASK) == 0) a_valid = false;
    if (tid == 129 && ((bm + 128) & LMASK) == 0) a_valid = false;
    if (a_grow < 0) a_grow = 0;
    if (a_grow >= M) a_grow = M - 1;
    const uint32_t a_sz = a_valid ? 16u : 0u;

    auto issueA = [&](int kc) {
        if (!a_active) return;
        uint32_t dst = sb + (uint32_t)(kc & 1) * A_SLOT + (uint32_t)tid * ASTR;
        const __half* ph = Ah + a_grow * D2 + kc * 32;
        const __half* pl = Al + a_grow * D2 + kc * 32;
#pragma unroll
        for (int i = 0; i < 4; i++) {
            cp16(dst + i * 16, ph + i * 8, a_sz);
            cp16(dst + A_PL + i * 16, pl + i * 8, a_sz);
        }
    };

    const int blr = tid >> 1;      // only rows < 32 used
    const int blseg = tid & 1;
    auto issueB = [&](int cc) {
        if (tid >= 64) return;
        int koff = cc % 3;
        int kc = cc / 3;
        uint32_t dst = sb + B_BASE + (uint32_t)(cc & 3) * BCG_B_SLOT +
                       (uint32_t)blr * ASTR + (uint32_t)blseg * 32;
        size_t bo = ((size_t)koff * 32 + blr) * D2 + kc * 32 + blseg * 16;
        cp16(dst, Wbc + bo, 16u);
        cp16(dst + 16, Wbc + bo + 8, 16u);
    };

    issueA(0); issueB(0); cp_commit();
    issueB(1); cp_commit();
    issueB(2); cp_commit();

    const int a_row = wid * 16 + (lane & 15);
    const uint32_t a_kb = (uint32_t)(lane >> 4) * 16;
    const int mi = lane >> 3;
    const int b_row = ((mi >> 1) << 3) + (lane & 7);
    const uint32_t b_kb = (uint32_t)(mi & 1) * 16;

    for (int cc = 0; cc < nch; cc++) {
        int rem = nch - 1 - cc;
        if (rem >= 2) cp_wait<2>();
        else if (rem == 1) cp_wait<1>();
        else cp_wait<0>();
        __syncthreads();
        if (cc + 3 < nch) {
            int nx = cc + 3;
            issueB(nx);
            if (nx % 3 == 0) issueA(nx / 3);
            cp_commit();
        }

        const int koff = cc % 3;
        const int kc = cc / 3;
        const uint32_t abase = sb + (uint32_t)(kc & 1) * A_SLOT;
        const uint32_t bbase = sb + B_BASE + (uint32_t)(cc & 3) * BCG_B_SLOT;

#pragma unroll
        for (int k16 = 0; k16 < 2; k16++) {
            uint32_t ah[4], al[4];
            {
                uint32_t addr = abase + (uint32_t)(a_row + koff) * ASTR +
                                (uint32_t)k16 * 32 + a_kb;
                ldsm4(ah, addr);
                ldsm4(al, addr + A_PL);
            }
            uint32_t bf[4][2];
#pragma unroll
            for (int p = 0; p < 2; p++) {
                uint32_t addr = bbase + (uint32_t)(b_row + p * 16) * ASTR +
                                (uint32_t)k16 * 32 + b_kb;
                uint32_t t4[4];
                ldsm4(t4, addr);
                bf[2 * p][0] = t4[0]; bf[2 * p][1] = t4[1];
                bf[2 * p + 1][0] = t4[2]; bf[2 * p + 1][1] = t4[3];
            }
#pragma unroll
            for (int nt = 0; nt < 4; nt++)
                hmma(acc[nt], ah, bf[nt]);
#pragma unroll
            for (int nt = 0; nt < 4; nt++)
                hmma(acc[nt], al, bf[nt]);
        }
    }

    // epilogue: thread holds Bm cols (nt 0,1) and matching Cm cols (nt+2).
    const int colB0 = (lane & 3) * 2;
#pragma unroll
    for (int h = 0; h < 2; h++) {
        int row = bm + wid * 16 + (lane >> 2) + h * 8;
        float s = 0.f;
#pragma unroll
        for (int nt = 0; nt < 2; nt++) {
#pragma unroll
            for (int q = 0; q < 2; q++) {
                int c = colB0 + nt * 8 + q;
                float pb = acc[nt][2 * h + q] + b2[c];
                float pc = acc[nt + 2][2 * h + q] + b3[c];
                s += pb * pc;
            }
        }
        s += __shfl_xor_sync(0xffffffffu, s, 1);
        s += __shfl_xor_sync(0xffffffffu, s, 2);
        if ((lane & 3) == 0) cbout[row] = s;
    }
}

// ---------------- launch ----------------
extern "C" void kernel_launch(void* const* d_in, const int* in_sizes, int n_in,
                              void* d_out, int out_size) {
    const float* x      = (const float*)d_in[0];
    const float* norm_w = (const float*)d_in[1];
    const float* inp_w  = (const float*)d_in[2];
    const float* inp_b  = (const float*)d_in[3];
    const float* conv_w = (const float*)d_in[4];
    const float* conv_b = (const float*)d_in[5];
    const float* cl_w   = (const float*)d_in[6];
    const float* cl_b   = (const float*)d_in[7];
    const float* fc1_w  = (const float*)d_in[8];
    const float* fc1_b  = (const float*)d_in[9];
    const float* fc2_w  = (const float*)d_in[10];
    const float* fc2_b  = (const float*)d_in[11];
    const float* fc3_w  = (const float*)d_in[12];
    const float* fc3_b  = (const float*)d_in[13];
    // d_in[14] = A (mathematically dead)
    const float* res_w  = (const float*)d_in[15];
    const float* res_b  = (const float*)d_in[16];
    const float* out_w  = (const float*)d_in[17];
    const float* out_b  = (const float*)d_in[18];

    int M = in_sizes[0] / D1;  // 16384

    __half *xnh, *xnl, *t0h, *t0l, *t1h, *t1l, *t2h, *t2l, *t3h, *t3l;
    __half *wIR, *wCnv, *wCl, *wF1, *wOut, *wBC;
    float *cb, *biasIR;
    cudaGetSymbolAddress((void**)&xnh, g_xnh);
    cudaGetSymbolAddress((void**)&xnl, g_xnl);
    cudaGetSymbolAddress((void**)&t0h, g_t0h);
    cudaGetSymbolAddress((void**)&t0l, g_t0l);
    cudaGetSymbolAddress((void**)&t1h, g_t1h);
    cudaGetSymbolAddress((void**)&t1l, g_t1l);
    cudaGetSymbolAddress((void**)&t2h, g_t2h);
    cudaGetSymbolAddress((void**)&t2l, g_t2l);
    cudaGetSymbolAddress((void**)&t3h, g_t3h);
    cudaGetSymbolAddress((void**)&t3l, g_t3l);
    cudaGetSymbolAddress((void**)&cb, g_cb);
    cudaGetSymbolAddress((void**)&wIR, g_wIR);
    cudaGetSymbolAddress((void**)&wCnv, g_wCnv);
    cudaGetSymbolAddress((void**)&wCl, g_wCl);
    cudaGetSymbolAddress((void**)&wF1, g_wF1);
    cudaGetSymbolAddress((void**)&wOut, g_wOut);
    cudaGetSymbolAddress((void**)&wBC, g_wBC);
    cudaGetSymbolAddress((void**)&biasIR, g_biasIR);

    cudaFuncSetAttribute(mm_h<0, 0>, cudaFuncAttributeMaxDynamicSharedMemorySize, GEMM_SMEM);
    cudaFuncSetAttribute(mm_h<1, 0>, cudaFuncAttributeMaxDynamicSharedMemorySize, GEMM_SMEM);
    cudaFuncSetAttribute(mm_h<2, 0>, cudaFuncAttributeMaxDynamicSharedMemorySize, GEMM_SMEM);
    cudaFuncSetAttribute(mm_h<3, 0>, cudaFuncAttributeMaxDynamicSharedMemorySize, GEMM_SMEM);
    cudaFuncSetAttribute(mm_h<0, 1>, cudaFuncAttributeMaxDynamicSharedMemorySize, GEMM_SMEM);
    cudaFuncSetAttribute(bcg, cudaFuncAttributeMaxDynamicSharedMemorySize, BCG_SMEM);

    // 1) prep: all weight transposes + rmsnorm + bias concat (one launch)
    prep<<<22216, 256>>>(x, norm_w, inp_w, conv_w, cl_w, fc1_w, res_w, out_w,
                         fc2_w, fc3_w, inp_b, res_b, xnh, xnl,
                         wIR, wCnv, wCl, wF1, wOut, wBC, biasIR);

    dim3 blk(256);
    dim3 g_fuse(2048 / 128, M / 128);  // 16 x 128
    dim3 g_big(D2 / 128, M / 128);     // 8 x 128
    dim3 g_out(D1 / 128, M / 128);     // 4 x 128

    // 2) fused: t0 = conv(xn, inp) [cols 0-1023]; t3 = swish(conv(xn, res)) [cols 1024-2047]
    mm_h<3, 0><<<g_fuse, blk, GEMM_SMEM>>>(xnh, xnl, wIR, biasIR, D1, 2048, M,
        t0h, t0l, nullptr, t3h, t3l, nullptr, nullptr, nullptr, nullptr, nullptr);
    // 3) t1 = swish(conv(t0, conv))
    mm_h<1, 0><<<g_big, blk, GEMM_SMEM>>>(t0h, t0l, wCnv, conv_b, D2, D2, M,
        t1h, t1l, nullptr, nullptr, nullptr, nullptr, nullptr, nullptr, nullptr, nullptr);
    // 4) t2 = conv(t1, cl) = x_conv_out
    mm_h<0, 0><<<g_big, blk, GEMM_SMEM>>>(t1h, t1l, wCl, cl_b, D2, D2, M,
        t2h, t2l, nullptr, nullptr, nullptr, nullptr, nullptr, nullptr, nullptr, nullptr);
    // 5) cb[m] via skinny HMMA GEMM
    bcg<<<M / 128, blk, BCG_SMEM>>>(t2h, t2l, wBC, fc2_b, fc3_b, cb, M);
    // 6) t0 = x_ssm * x_res (s6 epilogue; xc = t2, xr = t3)
    mm_h<2, 0><<<g_big, blk, GEMM_SMEM>>>(t2h, t2l, wF1, fc1_b, D2, D2, M,
        t0h, t0l, nullptr, nullptr, nullptr, t2h, t2l, t3h, t3l, cb);
    // 7) out = conv(t0, out) -> fp32 d_out
    mm_h<0, 1><<<g_out, blk, GEMM_SMEM>>>(t0h, t0l, wOut, out_b, D2, D1, M,
        nullptr, nullptr, (float*)d_out, nullptr, nullptr, nullptr, nullptr, nullptr, nullptr, nullptr);
}